// round 16
// baseline (speedup 1.0000x reference)
#include <cuda_runtime.h>
#include <cuda_fp16.h>
#include <math.h>
#include <stdint.h>

constexpr int kT    = 1024;
constexpr int kH    = 1024;
constexpr int kI    = 512;
constexpr int kE    = 16;
constexpr int kEAll = 18;     // + 2 shared-expert halves
constexpr int kTopK = 4;
constexpr int kNG   = 4;
constexpr int kGS   = kE / kNG;
constexpr int kTKG  = 2;
constexpr int kISH  = 1024;
constexpr float kScale = 2.5f;

// smem pipeline geometry (halves)
constexpr int kChunk  = 64;
constexpr int kAStrH  = 72;
constexpr int kBStrH  = 136;
constexpr int kAStageH = 128 * kAStrH;         // 9216 halves
constexpr int kBStageH = kChunk * kBStrH;      // 8704 halves
constexpr int kStageB  = (kAStageH + kBStageH) * 2;   // 35840 bytes
constexpr int kStages  = 3;
constexpr int kSmem    = kStages * kStageB;    // 107520 B -> 2 CTAs/SM

// ---- device scratch ----
__device__ int    g_cnt[kEAll];
__device__ int    g_tok[kEAll * kT];
__device__ float  g_coef[kEAll * kT];
__device__ int    g_tslot[kT * kTopK];
__device__ __half g_h[(size_t)kEAll * kT * kI];
__device__ __half g_o[(size_t)kEAll * kT * kH];   // fp16 partials (combine sums fp32)
// fp16-pre-rounded copies
__device__ __half g_rx[kT * kH];
__device__ __half g_rwg[(size_t)kE * kH * kI];
__device__ __half g_rwu[(size_t)kE * kH * kI];
__device__ __half g_rwd[(size_t)kE * kI * kH];
__device__ __half g_rswg[kH * kISH];
__device__ __half g_rswu[kH * kISH];
__device__ __half g_rswd[kISH * kH];

// ---------------------------------------------------------------------------
__device__ __forceinline__ uint32_t smem_u32(const void* p) {
    uint32_t a;
    asm("{ .reg .u64 t; cvta.to.shared.u64 t, %1; cvt.u32.u64 %0, t; }"
        : "=r"(a) : "l"(p));
    return a;
}
__device__ __forceinline__ void cp16(uint32_t dst, const void* src) {
    asm volatile("cp.async.cg.shared.global [%0], [%1], 16;" :: "r"(dst), "l"(src));
}
__device__ __forceinline__ void cp_commit() {
    asm volatile("cp.async.commit_group;" ::: "memory");
}
__device__ __forceinline__ void cp_wait1() {
    asm volatile("cp.async.wait_group 1;" ::: "memory");
}
__device__ __forceinline__ void ldsm4(uint32_t* r, uint32_t a) {
    asm volatile("ldmatrix.sync.aligned.m8n8.x4.shared.b16 {%0,%1,%2,%3}, [%4];"
                 : "=r"(r[0]), "=r"(r[1]), "=r"(r[2]), "=r"(r[3]) : "r"(a));
}
__device__ __forceinline__ void ldsm4t(uint32_t* r, uint32_t a) {
    asm volatile("ldmatrix.sync.aligned.m8n8.x4.trans.shared.b16 {%0,%1,%2,%3}, [%4];"
                 : "=r"(r[0]), "=r"(r[1]), "=r"(r[2]), "=r"(r[3]) : "r"(a));
}
__device__ __forceinline__ void mma16(float* c, const uint32_t* a,
                                      uint32_t b0, uint32_t b1) {
    asm volatile("mma.sync.aligned.m16n8k16.row.col.f32.f16.f16.f32 "
                 "{%0,%1,%2,%3},{%4,%5,%6,%7},{%8,%9},{%0,%1,%2,%3};\n"
                 : "+f"(c[0]), "+f"(c[1]), "+f"(c[2]), "+f"(c[3])
                 : "r"(a[0]), "r"(a[1]), "r"(a[2]), "r"(a[3]), "r"(b0), "r"(b1));
}

// ---------------------------------------------------------------------------
__global__ void init_kernel() {
    int i = blockIdx.x * blockDim.x + threadIdx.x;
    if (i < kE) g_cnt[i] = 0;
    if (i == kE || i == kE + 1) g_cnt[i] = kT;
    if (i < kT) {
        g_tok[kE * kT + i] = i;       g_coef[kE * kT + i] = 1.f;
        g_tok[(kE + 1) * kT + i] = i; g_coef[(kE + 1) * kT + i] = 1.f;
    }
}

// ---------------------------------------------------------------------------
// Fused router+x-convert (blocks 0..1023) + fp16 preround of wg/wu/swg/swu.
constexpr size_t kF4W = (size_t)kE * kH * kI / 4;
constexpr size_t kF4S = (size_t)kH * kISH / 4;
constexpr int    kPreBlocks = 1024;

__global__ __launch_bounds__(512) void front_kernel(
    const float* __restrict__ x, const float* __restrict__ rw,
    const float* __restrict__ ebias,
    const float4* __restrict__ wg,  const float4* __restrict__ wu,
    const float4* __restrict__ swg, const float4* __restrict__ swu)
{
    if (blockIdx.x >= kT) {
        // ---- preround role (wg, wu, swg, swu) ----
        const size_t total = 2 * kF4W + 2 * kF4S;
        const size_t stride = (size_t)kPreBlocks * 512;
        for (size_t i = (size_t)(blockIdx.x - kT) * 512 + threadIdx.x;
             i < total; i += stride) {
            const float4* src; __half* dst; size_t j = i;
            if      (j < kF4W)           { src = wg;  dst = g_rwg; }
            else if ((j -= kF4W) < kF4W) { src = wu;  dst = g_rwu; }
            else if ((j -= kF4W) < kF4S) { src = swg; dst = g_rswg; }
            else { j -= kF4S;              src = swu; dst = g_rswu; }
            float4 v = src[j];
            __half2* d2 = (__half2*)(dst + j * 4);
            d2[0] = __floats2half2_rn(v.x, v.y);
            d2[1] = __floats2half2_rn(v.z, v.w);
        }
        return;
    }
    // ---- router + x-convert role ----
    const int t = blockIdx.x;
    const int warp = threadIdx.x >> 5;
    const int lane = threadIdx.x & 31;
    __shared__ float logits[kE];

    const float* xr = x + (size_t)t * kH;

    // convert this token's x row to fp16 (512 threads x 2 elems, float2-wide)
    {
        const float2* xr2 = (const float2*)xr;
        __half2* d2 = (__half2*)(g_rx + (size_t)t * kH);
        float2 v = xr2[threadIdx.x];
        d2[threadIdx.x] = __floats2half2_rn(v.x, v.y);
    }

    float acc = 0.f;
    for (int h = lane; h < kH; h += 32)
        acc += xr[h] * rw[h * kE + warp];
    #pragma unroll
    for (int o = 16; o; o >>= 1) acc += __shfl_xor_sync(0xffffffffu, acc, o);
    if (lane == 0) logits[warp] = acc;
    __syncthreads();

    if (threadIdx.x == 0) {
        float scores[kE], sc[kE];
        #pragma unroll
        for (int e = 0; e < kE; e++) {
            float s = 1.f / (1.f + expf(-logits[e]));
            scores[e] = s;
            sc[e] = s + ebias[e];
        }
        float gs[kNG];
        #pragma unroll
        for (int g = 0; g < kNG; g++) {
            float m1 = -1e30f, m2 = -1e30f;
            #pragma unroll
            for (int j = 0; j < kGS; j++) {
                float v = sc[g * kGS + j];
                if (v > m1) { m2 = m1; m1 = v; }
                else if (v > m2) m2 = v;
            }
            gs[g] = m1 + m2;
        }
        bool gsel[kNG] = {false, false, false, false};
        for (int k = 0; k < kTKG; k++) {
            int bi = -1; float bv = -1e30f;
            for (int g = 0; g < kNG; g++)
                if (!gsel[g] && gs[g] > bv) { bv = gs[g]; bi = g; }
            gsel[bi] = true;
        }
        float masked[kE];
        #pragma unroll
        for (int e = 0; e < kE; e++)
            masked[e] = gsel[e / kGS] ? sc[e] : 0.f;
        int tidx[kTopK]; float w[kTopK]; float wsum = 0.f;
        bool used[kE];
        #pragma unroll
        for (int e = 0; e < kE; e++) used[e] = false;
        for (int k = 0; k < kTopK; k++) {
            int bi = -1; float bv = -1e30f;
            for (int e = 0; e < kE; e++)
                if (!used[e] && masked[e] > bv) { bv = masked[e]; bi = e; }
            used[bi] = true;
            tidx[k] = bi;
            w[k] = scores[bi];
            wsum += w[k];
        }
        float inv = kScale / (wsum + 1e-20f);
        for (int k = 0; k < kTopK; k++) {
            int e = tidx[k];
            int slot = atomicAdd(&g_cnt[e], 1);
            g_tok[e * kT + slot]  = t;
            g_coef[e * kT + slot] = w[k] * inv;
            g_tslot[t * kTopK + k] = e * kT + slot;
        }
    }
}

// ---------------------------------------------------------------------------
// Gate+up (z < 18): 256-thread CTA, tile 128 rows x 64 I-cols;
//   smem B = [64 g | 64 u]; 8 warps mb=(w&3)*32, nb=(w>>2)*32; fp16 mma+ldmatrix.
// Preround role (z >= 18): converts wd/swd to fp16, overlapped with MMA CTAs.
__global__ __launch_bounds__(256, 2) void gateup_v9(
    const float4* __restrict__ wd, const float4* __restrict__ swd)
{
    if (blockIdx.z >= kEAll) {
        const size_t total = kF4W + kF4S;
        size_t i = (((size_t)(blockIdx.z - kEAll) * 64 +
                     blockIdx.y * 8 + blockIdx.x) * 256 + threadIdx.x);
        const size_t stride = 128 * 256;
        for (; i < total; i += stride) {
            const float4* src; __half* dst; size_t j = i;
            if (j < kF4W) { src = wd;  dst = g_rwd; }
            else { j -= kF4W; src = swd; dst = g_rswd; }
            float4 v = src[j];
            __half2* d2 = (__half2*)(dst + j * 4);
            d2[0] = __floats2half2_rn(v.x, v.y);
            d2[1] = __floats2half2_rn(v.z, v.w);
        }
        return;
    }
    const int e = blockIdx.z;
    const int cnt = g_cnt[e];
    const int row0 = blockIdx.y * 128;
    if (row0 >= cnt) return;
    const int col0 = blockIdx.x * 64;

    extern __shared__ __half sm[];
    const uint32_t smb = smem_u32(sm);

    const int tid = threadIdx.x;
    const int w = tid >> 5, l = tid & 31;
    const int qr = l >> 2, qc = l & 3;
    const int mb = (w & 3) * 32, nb = (w >> 2) * 32;

    const __half *gb, *ub; int ldb;
    if (e < kE) {
        gb = g_rwg + (size_t)e * kH * kI;
        ub = g_rwu + (size_t)e * kH * kI;
        ldb = kI;
    } else {
        int off = (e - kE) * kI;
        gb = g_rswg + off; ub = g_rswu + off; ldb = kISH;
    }

    int aslot = row0 + (tid >> 1); if (aslot >= cnt) aslot = cnt - 1;
    const __half* abase = g_rx + (size_t)g_tok[e * kT + aslot] * kH + (tid & 1) * 32;
    const uint32_t aoff0 = ((tid >> 1) * kAStrH + (tid & 1) * 32) * 2;
    const int ng = tid & 15;
    const __half* bbase = ((ng < 8) ? (gb + col0 + ng * 8)
                                    : (ub + col0 + (ng - 8) * 8))
                          + (size_t)(tid >> 4) * ldb;
    const uint32_t boff0 = (kAStageH + (tid >> 4) * kBStrH + ng * 8) * 2;

    const uint32_t aF = (mb + ((l >> 3) & 1) * 8 + (l & 7)) * kAStrH + (l >> 4) * 8;
    const uint32_t bF = (((l >> 3) & 1) * 8 + (l & 7)) * kBStrH + (l >> 4) * 8;

    float cg[2][4][4] = {}, cu[2][4][4] = {};

    constexpr int NCH = kH / kChunk;   // 16
    auto issue = [&](int ch, int s) {
        const uint32_t sb = smb + s * kStageB;
        const int k0 = ch * kChunk;
        #pragma unroll
        for (int p = 0; p < 4; p++)
            cp16(sb + aoff0 + p * 16, abase + k0 + p * 8);
        #pragma unroll
        for (int p = 0; p < 4; p++)
            cp16(sb + boff0 + p * (16 * kBStrH * 2),
                 bbase + (size_t)(k0 + 16 * p) * ldb);
    };
    issue(0, 0); cp_commit();
    issue(1, 1); cp_commit();

    for (int ch = 0; ch < NCH; ch++) {
        cp_wait1();
        __syncthreads();
        if (ch + 2 < NCH) { issue(ch + 2, (ch + 2) % 3); }
        cp_commit();
        const uint32_t sA = smb + (ch % 3) * kStageB;
        const uint32_t sB = sA + kAStageH * 2;
        #pragma unroll
        for (int ks = 0; ks < kChunk; ks += 16) {
            uint32_t a[2][4];
            #pragma unroll
            for (int mt = 0; mt < 2; mt++)
                ldsm4(a[mt], sA + (aF + mt * 16 * kAStrH + ks) * 2);
            #pragma unroll
            for (int blk = 0; blk < 2; blk++) {
                uint32_t bg[4], bu[4];
                uint32_t bad = sB + (bF + ks * kBStrH + nb + blk * 16) * 2;
                ldsm4t(bg, bad);
                ldsm4t(bu, bad + 64 * 2);
                #pragma unroll
                for (int sub = 0; sub < 2; sub++) {
                    int nt = blk * 2 + sub;
                    #pragma unroll
                    for (int mt = 0; mt < 2; mt++) {
                        mma16(cg[mt][nt], a[mt], bg[sub * 2], bg[sub * 2 + 1]);
                        mma16(cu[mt][nt], a[mt], bu[sub * 2], bu[sub * 2 + 1]);
                    }
                }
            }
        }
    }

    // Epilogue: h = coef * silu(g) * u  (fp16 for the down GEMM)
    #pragma unroll
    for (int mt = 0; mt < 2; mt++) {
        #pragma unroll
        for (int pair = 0; pair < 2; pair++) {
            int r = row0 + mb + mt * 16 + qr + pair * 8;
            if (r < cnt) {
                float cf = g_coef[e * kT + r];
                __half* hp = g_h + ((size_t)e * kT + r) * kI + col0 + nb;
                #pragma unroll
                for (int nt = 0; nt < 4; nt++) {
                    float g0 = cg[mt][nt][pair * 2 + 0];
                    float g1 = cg[mt][nt][pair * 2 + 1];
                    float u0 = cu[mt][nt][pair * 2 + 0];
                    float u1 = cu[mt][nt][pair * 2 + 1];
                    float h0 = cf * (g0 / (1.f + __expf(-g0))) * u0;
                    float h1 = cf * (g1 / (1.f + __expf(-g1))) * u1;
                    *(__half2*)&hp[nt * 8 + 2 * qc] = __floats2half2_rn(h0, h1);
                }
            }
        }
    }
}

// ---------------------------------------------------------------------------
// Down-proj: 256-thread CTA, tile 128 rows x 128 H-cols.
// 8 warps: mb=(w&3)*32, nw=(w>>2)*64. fp16 m16n8k16 + ldmatrix. 2 CTAs/SM.
// Epilogue stores fp16 partials to g_o (combine sums in fp32).
__global__ __launch_bounds__(256, 2) void down_v9() {
    const int e = blockIdx.z;
    const int cnt = g_cnt[e];
    const int row0 = blockIdx.y * 128;
    if (row0 >= cnt) return;
    const int col0 = blockIdx.x * 128;

    extern __shared__ __half sm[];
    const uint32_t smb = smem_u32(sm);

    const int tid = threadIdx.x;
    const int w = tid >> 5, l = tid & 31;
    const int qr = l >> 2, qc = l & 3;
    const int mb = (w & 3) * 32, nw = (w >> 2) * 64;

    const __half* bw = (e < kE) ? (g_rwd + (size_t)e * kI * kH)
                                : (g_rswd + (size_t)(e - kE) * kI * kH);

    const __half* abase = g_h + ((size_t)e * kT + row0 + (tid >> 1)) * kI + (tid & 1) * 32;
    const uint32_t aoff0 = ((tid >> 1) * kAStrH + (tid & 1) * 32) * 2;
    const int ng = tid & 15;
    const __half* bbase = bw + col0 + ng * 8 + (size_t)(tid >> 4) * kH;
    const uint32_t boff0 = (kAStageH + (tid >> 4) * kBStrH + ng * 8) * 2;

    const uint32_t aF = (mb + ((l >> 3) & 1) * 8 + (l & 7)) * kAStrH + (l >> 4) * 8;
    const uint32_t bF = (((l >> 3) & 1) * 8 + (l & 7)) * kBStrH + (l >> 4) * 8;

    float c[2][8][4] = {};

    constexpr int NCH = kI / kChunk;   // 8
    auto issue = [&](int ch, int s) {
        const uint32_t sb = smb + s * kStageB;
        const int k0 = ch * kChunk;
        #pragma unroll
        for (int p = 0; p < 4; p++)
            cp16(sb + aoff0 + p * 16, abase + k0 + p * 8);
        #pragma unroll
        for (int p = 0; p < 4; p++)
            cp16(sb + boff0 + p * (16 * kBStrH * 2),
                 bbase + (size_t)(k0 + 16 * p) * kH);
    };
    issue(0, 0); cp_commit();
    issue(1, 1); cp_commit();

    for (int ch = 0; ch < NCH; ch++) {
        cp_wait1();
        __syncthreads();
        if (ch + 2 < NCH) { issue(ch + 2, (ch + 2) % 3); }
        cp_commit();
        const uint32_t sA = smb + (ch % 3) * kStageB;
        const uint32_t sB = sA + kAStageH * 2;
        #pragma unroll
        for (int ks = 0; ks < kChunk; ks += 16) {
            uint32_t a[2][4];
            #pragma unroll
            for (int mt = 0; mt < 2; mt++)
                ldsm4(a[mt], sA + (aF + mt * 16 * kAStrH + ks) * 2);
            #pragma unroll
            for (int blk = 0; blk < 4; blk++) {
                uint32_t b[4];
                ldsm4t(b, sB + (bF + ks * kBStrH + nw + blk * 16) * 2);
                #pragma unroll
                for (int sub = 0; sub < 2; sub++) {
                    int nt = blk * 2 + sub;
                    #pragma unroll
                    for (int mt = 0; mt < 2; mt++)
                        mma16(c[mt][nt], a[mt], b[sub * 2], b[sub * 2 + 1]);
                }
            }
        }
    }

    #pragma unroll
    for (int mt = 0; mt < 2; mt++) {
        #pragma unroll
        for (int pair = 0; pair < 2; pair++) {
            int r = row0 + mb + mt * 16 + qr + pair * 8;
            if (r < cnt) {
                __half* op = g_o + ((size_t)e * kT + r) * kH + col0 + nw;
                #pragma unroll
                for (int nt = 0; nt < 8; nt++) {
                    *(__half2*)&op[nt * 8 + 2 * qc] =
                        __floats2half2_rn(c[mt][nt][pair * 2 + 0],
                                          c[mt][nt][pair * 2 + 1]);
                }
            }
        }
    }
}

// ---------------------------------------------------------------------------
// Combine: out[t] = sum of 4 routed + 2 shared fp16 partial rows (fp32 sum).
__global__ __launch_bounds__(256) void combine_kernel(float* __restrict__ out) {
    const int t = blockIdx.x;
    const int c = threadIdx.x * 4;
    int s[6];
    s[0] = g_tslot[t * kTopK + 0]; s[1] = g_tslot[t * kTopK + 1];
    s[2] = g_tslot[t * kTopK + 2]; s[3] = g_tslot[t * kTopK + 3];
    s[4] = kE * kT + t;            s[5] = (kE + 1) * kT + t;
    float2 acc0 = make_float2(0.f, 0.f), acc1 = make_float2(0.f, 0.f);
    #pragma unroll
    for (int i = 0; i < 6; i++) {
        const __half2* p = (const __half2*)&g_o[(size_t)s[i] * kH + c];
        float2 v0 = __half22float2(p[0]);
        float2 v1 = __half22float2(p[1]);
        acc0.x += v0.x; acc0.y += v0.y;
        acc1.x += v1.x; acc1.y += v1.y;
    }
    float4 r; r.x = acc0.x; r.y = acc0.y; r.z = acc1.x; r.w = acc1.y;
    *(float4*)&out[(size_t)t * kH + c] = r;
}

// ---------------------------------------------------------------------------
extern "C" void kernel_launch(void* const* d_in, const int* in_sizes, int n_in,
                              void* d_out, int out_size) {
    const float* x   = (const float*)d_in[0];
    const float* rw  = (const float*)d_in[1];
    const float* eb  = (const float*)d_in[2];
    const float* wg  = (const float*)d_in[3];
    const float* wu  = (const float*)d_in[4];
    const float* wd  = (const float*)d_in[5];
    const float* swg = (const float*)d_in[6];
    const float* swu = (const float*)d_in[7];
    const float* swd = (const float*)d_in[8];
    float* out = (float*)d_out;

    cudaFuncSetAttribute(gateup_v9, cudaFuncAttributeMaxDynamicSharedMemorySize, kSmem);
    cudaFuncSetAttribute(down_v9,   cudaFuncAttributeMaxDynamicSharedMemorySize, kSmem);

    init_kernel<<<4, 256>>>();
    front_kernel<<<kT + kPreBlocks, 512>>>(x, rw, eb,
                                           (const float4*)wg, (const float4*)wu,
                                           (const float4*)swg, (const float4*)swu);
    gateup_v9<<<dim3(8, 8, kEAll + 2), 256, kSmem>>>((const float4*)wd,
                                                     (const float4*)swd);
    down_v9<<<dim3(8, 8, kEAll), 256, kSmem>>>();
    combine_kernel<<<kT, 256>>>(out);
}

// round 17
// speedup vs baseline: 1.4461x; 1.4461x over previous
#include <cuda_runtime.h>
#include <cuda_fp16.h>
#include <math.h>
#include <stdint.h>

constexpr int kT    = 1024;
constexpr int kH    = 1024;
constexpr int kI    = 512;
constexpr int kE    = 16;
constexpr int kEAll = 18;     // + 2 shared-expert halves
constexpr int kTopK = 4;
constexpr int kNG   = 4;
constexpr int kGS   = kE / kNG;
constexpr int kTKG  = 2;
constexpr int kISH  = 1024;
constexpr float kScale = 2.5f;

// smem pipeline geometry (halves)
constexpr int kChunk  = 64;
constexpr int kAStrH  = 72;
constexpr int kBStrH  = 136;
constexpr int kAStageH = 128 * kAStrH;         // 9216 halves
constexpr int kBStageH = kChunk * kBStrH;      // 8704 halves
constexpr int kStageB  = (kAStageH + kBStageH) * 2;   // 35840 bytes
constexpr int kStages  = 3;
constexpr int kSmem    = kStages * kStageB;    // 107520 B -> 2 CTAs/SM

// ---- device scratch ----
__device__ int    g_cnt[kEAll];
__device__ int    g_tok[kEAll * kT];
__device__ float  g_coef[kEAll * kT];
__device__ int    g_tslot[kT * kTopK];
__device__ __half g_h[(size_t)kEAll * kT * kI];
__device__ __half g_o[(size_t)kEAll * kT * kH];   // fp16 partials (combine sums fp32)
// fp16-pre-rounded copies
__device__ __half g_rx[kT * kH];
__device__ __half g_rwg[(size_t)kE * kH * kI];
__device__ __half g_rwu[(size_t)kE * kH * kI];
__device__ __half g_rwd[(size_t)kE * kI * kH];
__device__ __half g_rswg[kH * kISH];
__device__ __half g_rswu[kH * kISH];
__device__ __half g_rswd[kISH * kH];

// ---------------------------------------------------------------------------
__device__ __forceinline__ uint32_t smem_u32(const void* p) {
    uint32_t a;
    asm("{ .reg .u64 t; cvta.to.shared.u64 t, %1; cvt.u32.u64 %0, t; }"
        : "=r"(a) : "l"(p));
    return a;
}
__device__ __forceinline__ void cp16(uint32_t dst, const void* src) {
    asm volatile("cp.async.cg.shared.global [%0], [%1], 16;" :: "r"(dst), "l"(src));
}
__device__ __forceinline__ void cp_commit() {
    asm volatile("cp.async.commit_group;" ::: "memory");
}
__device__ __forceinline__ void cp_wait1() {
    asm volatile("cp.async.wait_group 1;" ::: "memory");
}
__device__ __forceinline__ void ldsm4(uint32_t* r, uint32_t a) {
    asm volatile("ldmatrix.sync.aligned.m8n8.x4.shared.b16 {%0,%1,%2,%3}, [%4];"
                 : "=r"(r[0]), "=r"(r[1]), "=r"(r[2]), "=r"(r[3]) : "r"(a));
}
__device__ __forceinline__ void ldsm4t(uint32_t* r, uint32_t a) {
    asm volatile("ldmatrix.sync.aligned.m8n8.x4.trans.shared.b16 {%0,%1,%2,%3}, [%4];"
                 : "=r"(r[0]), "=r"(r[1]), "=r"(r[2]), "=r"(r[3]) : "r"(a));
}
__device__ __forceinline__ void mma16(float* c, const uint32_t* a,
                                      uint32_t b0, uint32_t b1) {
    asm volatile("mma.sync.aligned.m16n8k16.row.col.f32.f16.f16.f32 "
                 "{%0,%1,%2,%3},{%4,%5,%6,%7},{%8,%9},{%0,%1,%2,%3};\n"
                 : "+f"(c[0]), "+f"(c[1]), "+f"(c[2]), "+f"(c[3])
                 : "r"(a[0]), "r"(a[1]), "r"(a[2]), "r"(a[3]), "r"(b0), "r"(b1));
}

// ---------------------------------------------------------------------------
__global__ void init_kernel() {
    int i = blockIdx.x * blockDim.x + threadIdx.x;
    if (i < kE) g_cnt[i] = 0;
    if (i == kE || i == kE + 1) g_cnt[i] = kT;
    if (i < kT) {
        g_tok[kE * kT + i] = i;       g_coef[kE * kT + i] = 1.f;
        g_tok[(kE + 1) * kT + i] = i; g_coef[(kE + 1) * kT + i] = 1.f;
    }
}

// ---------------------------------------------------------------------------
// Fused router (blocks 0..1023) + fp16 preround of x/wg/wu/swg/swu.
constexpr size_t kF4X = (size_t)kT * kH / 4;
constexpr size_t kF4W = (size_t)kE * kH * kI / 4;
constexpr size_t kF4S = (size_t)kH * kISH / 4;
constexpr int    kPreBlocks = 1024;

__global__ __launch_bounds__(512) void front_kernel(
    const float* __restrict__ x, const float* __restrict__ rw,
    const float* __restrict__ ebias,
    const float4* __restrict__ wg,  const float4* __restrict__ wu,
    const float4* __restrict__ swg, const float4* __restrict__ swu)
{
    if (blockIdx.x >= kT) {
        const size_t total = kF4X + 2 * kF4W + 2 * kF4S;
        const size_t stride = (size_t)kPreBlocks * 512;
        for (size_t i = (size_t)(blockIdx.x - kT) * 512 + threadIdx.x;
             i < total; i += stride) {
            const float4* src; __half* dst; size_t j = i;
            if      (j < kF4X)           { src = (const float4*)x; dst = g_rx; }
            else if ((j -= kF4X) < kF4W) { src = wg;  dst = g_rwg; }
            else if ((j -= kF4W) < kF4W) { src = wu;  dst = g_rwu; }
            else if ((j -= kF4W) < kF4S) { src = swg; dst = g_rswg; }
            else { j -= kF4S;              src = swu; dst = g_rswu; }
            float4 v = src[j];
            __half2* d2 = (__half2*)(dst + j * 4);
            d2[0] = __floats2half2_rn(v.x, v.y);
            d2[1] = __floats2half2_rn(v.z, v.w);
        }
        return;
    }
    // ---- router role ----
    const int t = blockIdx.x;
    const int warp = threadIdx.x >> 5;
    const int lane = threadIdx.x & 31;
    __shared__ float logits[kE];

    const float* xr = x + (size_t)t * kH;
    float acc = 0.f;
    for (int h = lane; h < kH; h += 32)
        acc += xr[h] * rw[h * kE + warp];
    #pragma unroll
    for (int o = 16; o; o >>= 1) acc += __shfl_xor_sync(0xffffffffu, acc, o);
    if (lane == 0) logits[warp] = acc;
    __syncthreads();

    if (threadIdx.x == 0) {
        float scores[kE], sc[kE];
        #pragma unroll
        for (int e = 0; e < kE; e++) {
            float s = 1.f / (1.f + expf(-logits[e]));
            scores[e] = s;
            sc[e] = s + ebias[e];
        }
        float gs[kNG];
        #pragma unroll
        for (int g = 0; g < kNG; g++) {
            float m1 = -1e30f, m2 = -1e30f;
            #pragma unroll
            for (int j = 0; j < kGS; j++) {
                float v = sc[g * kGS + j];
                if (v > m1) { m2 = m1; m1 = v; }
                else if (v > m2) m2 = v;
            }
            gs[g] = m1 + m2;
        }
        bool gsel[kNG] = {false, false, false, false};
        for (int k = 0; k < kTKG; k++) {
            int bi = -1; float bv = -1e30f;
            for (int g = 0; g < kNG; g++)
                if (!gsel[g] && gs[g] > bv) { bv = gs[g]; bi = g; }
            gsel[bi] = true;
        }
        float masked[kE];
        #pragma unroll
        for (int e = 0; e < kE; e++)
            masked[e] = gsel[e / kGS] ? sc[e] : 0.f;
        int tidx[kTopK]; float w[kTopK]; float wsum = 0.f;
        bool used[kE];
        #pragma unroll
        for (int e = 0; e < kE; e++) used[e] = false;
        for (int k = 0; k < kTopK; k++) {
            int bi = -1; float bv = -1e30f;
            for (int e = 0; e < kE; e++)
                if (!used[e] && masked[e] > bv) { bv = masked[e]; bi = e; }
            used[bi] = true;
            tidx[k] = bi;
            w[k] = scores[bi];
            wsum += w[k];
        }
        float inv = kScale / (wsum + 1e-20f);
        for (int k = 0; k < kTopK; k++) {
            int e = tidx[k];
            int slot = atomicAdd(&g_cnt[e], 1);
            g_tok[e * kT + slot]  = t;
            g_coef[e * kT + slot] = w[k] * inv;
            g_tslot[t * kTopK + k] = e * kT + slot;
        }
    }
}

// ---------------------------------------------------------------------------
// Gate+up (z < 18): 256-thread CTA, tile 128 rows x 64 I-cols;
//   smem B = [64 g | 64 u]; 8 warps mb=(w&3)*32, nb=(w>>2)*32; fp16 mma+ldmatrix.
// Preround role (z >= 18): converts wd/swd to fp16, overlapped with MMA CTAs.
__global__ __launch_bounds__(256, 2) void gateup_v9(
    const float4* __restrict__ wd, const float4* __restrict__ swd)
{
    if (blockIdx.z >= kEAll) {
        const size_t total = kF4W + kF4S;
        size_t i = (((size_t)(blockIdx.z - kEAll) * 64 +
                     blockIdx.y * 8 + blockIdx.x) * 256 + threadIdx.x);
        const size_t stride = 128 * 256;
        for (; i < total; i += stride) {
            const float4* src; __half* dst; size_t j = i;
            if (j < kF4W) { src = wd;  dst = g_rwd; }
            else { j -= kF4W; src = swd; dst = g_rswd; }
            float4 v = src[j];
            __half2* d2 = (__half2*)(dst + j * 4);
            d2[0] = __floats2half2_rn(v.x, v.y);
            d2[1] = __floats2half2_rn(v.z, v.w);
        }
        return;
    }
    const int e = blockIdx.z;
    const int cnt = g_cnt[e];
    const int row0 = blockIdx.y * 128;
    if (row0 >= cnt) return;
    const int col0 = blockIdx.x * 64;

    extern __shared__ __half sm[];
    const uint32_t smb = smem_u32(sm);

    const int tid = threadIdx.x;
    const int w = tid >> 5, l = tid & 31;
    const int qr = l >> 2, qc = l & 3;
    const int mb = (w & 3) * 32, nb = (w >> 2) * 32;

    const __half *gb, *ub; int ldb;
    if (e < kE) {
        gb = g_rwg + (size_t)e * kH * kI;
        ub = g_rwu + (size_t)e * kH * kI;
        ldb = kI;
    } else {
        int off = (e - kE) * kI;
        gb = g_rswg + off; ub = g_rswu + off; ldb = kISH;
    }

    int aslot = row0 + (tid >> 1); if (aslot >= cnt) aslot = cnt - 1;
    const __half* abase = g_rx + (size_t)g_tok[e * kT + aslot] * kH + (tid & 1) * 32;
    const uint32_t aoff0 = ((tid >> 1) * kAStrH + (tid & 1) * 32) * 2;
    const int ng = tid & 15;
    const __half* bbase = ((ng < 8) ? (gb + col0 + ng * 8)
                                    : (ub + col0 + (ng - 8) * 8))
                          + (size_t)(tid >> 4) * ldb;
    const uint32_t boff0 = (kAStageH + (tid >> 4) * kBStrH + ng * 8) * 2;

    const uint32_t aF = (mb + ((l >> 3) & 1) * 8 + (l & 7)) * kAStrH + (l >> 4) * 8;
    const uint32_t bF = (((l >> 3) & 1) * 8 + (l & 7)) * kBStrH + (l >> 4) * 8;

    float cg[2][4][4] = {}, cu[2][4][4] = {};

    constexpr int NCH = kH / kChunk;   // 16
    auto issue = [&](int ch, int s) {
        const uint32_t sb = smb + s * kStageB;
        const int k0 = ch * kChunk;
        #pragma unroll
        for (int p = 0; p < 4; p++)
            cp16(sb + aoff0 + p * 16, abase + k0 + p * 8);
        #pragma unroll
        for (int p = 0; p < 4; p++)
            cp16(sb + boff0 + p * (16 * kBStrH * 2),
                 bbase + (size_t)(k0 + 16 * p) * ldb);
    };
    issue(0, 0); cp_commit();
    issue(1, 1); cp_commit();

    for (int ch = 0; ch < NCH; ch++) {
        cp_wait1();
        __syncthreads();
        if (ch + 2 < NCH) { issue(ch + 2, (ch + 2) % 3); }
        cp_commit();
        const uint32_t sA = smb + (ch % 3) * kStageB;
        const uint32_t sB = sA + kAStageH * 2;
        #pragma unroll
        for (int ks = 0; ks < kChunk; ks += 16) {
            uint32_t a[2][4];
            #pragma unroll
            for (int mt = 0; mt < 2; mt++)
                ldsm4(a[mt], sA + (aF + mt * 16 * kAStrH + ks) * 2);
            #pragma unroll
            for (int blk = 0; blk < 2; blk++) {
                uint32_t bg[4], bu[4];
                uint32_t bad = sB + (bF + ks * kBStrH + nb + blk * 16) * 2;
                ldsm4t(bg, bad);
                ldsm4t(bu, bad + 64 * 2);
                #pragma unroll
                for (int sub = 0; sub < 2; sub++) {
                    int nt = blk * 2 + sub;
                    #pragma unroll
                    for (int mt = 0; mt < 2; mt++) {
                        mma16(cg[mt][nt], a[mt], bg[sub * 2], bg[sub * 2 + 1]);
                        mma16(cu[mt][nt], a[mt], bu[sub * 2], bu[sub * 2 + 1]);
                    }
                }
            }
        }
    }

    // Epilogue: h = coef * silu(g) * u  (fp16 for the down GEMM)
    #pragma unroll
    for (int mt = 0; mt < 2; mt++) {
        #pragma unroll
        for (int pair = 0; pair < 2; pair++) {
            int r = row0 + mb + mt * 16 + qr + pair * 8;
            if (r < cnt) {
                float cf = g_coef[e * kT + r];
                __half* hp = g_h + ((size_t)e * kT + r) * kI + col0 + nb;
                #pragma unroll
                for (int nt = 0; nt < 4; nt++) {
                    float g0 = cg[mt][nt][pair * 2 + 0];
                    float g1 = cg[mt][nt][pair * 2 + 1];
                    float u0 = cu[mt][nt][pair * 2 + 0];
                    float u1 = cu[mt][nt][pair * 2 + 1];
                    float h0 = cf * (g0 / (1.f + __expf(-g0))) * u0;
                    float h1 = cf * (g1 / (1.f + __expf(-g1))) * u1;
                    *(__half2*)&hp[nt * 8 + 2 * qc] = __floats2half2_rn(h0, h1);
                }
            }
        }
    }
}

// ---------------------------------------------------------------------------
// Down-proj: 256-thread CTA, tile 128 rows x 128 H-cols.
// 8 warps: mb=(w&3)*32, nw=(w>>2)*64. fp16 m16n8k16 + ldmatrix. 2 CTAs/SM.
// Epilogue stores fp16 partials to g_o (combine sums in fp32).
__global__ __launch_bounds__(256, 2) void down_v9() {
    const int e = blockIdx.z;
    const int cnt = g_cnt[e];
    const int row0 = blockIdx.y * 128;
    if (row0 >= cnt) return;
    const int col0 = blockIdx.x * 128;

    extern __shared__ __half sm[];
    const uint32_t smb = smem_u32(sm);

    const int tid = threadIdx.x;
    const int w = tid >> 5, l = tid & 31;
    const int qr = l >> 2, qc = l & 3;
    const int mb = (w & 3) * 32, nw = (w >> 2) * 64;

    const __half* bw = (e < kE) ? (g_rwd + (size_t)e * kI * kH)
                                : (g_rswd + (size_t)(e - kE) * kI * kH);

    const __half* abase = g_h + ((size_t)e * kT + row0 + (tid >> 1)) * kI + (tid & 1) * 32;
    const uint32_t aoff0 = ((tid >> 1) * kAStrH + (tid & 1) * 32) * 2;
    const int ng = tid & 15;
    const __half* bbase = bw + col0 + ng * 8 + (size_t)(tid >> 4) * kH;
    const uint32_t boff0 = (kAStageH + (tid >> 4) * kBStrH + ng * 8) * 2;

    const uint32_t aF = (mb + ((l >> 3) & 1) * 8 + (l & 7)) * kAStrH + (l >> 4) * 8;
    const uint32_t bF = (((l >> 3) & 1) * 8 + (l & 7)) * kBStrH + (l >> 4) * 8;

    float c[2][8][4] = {};

    constexpr int NCH = kI / kChunk;   // 8
    auto issue = [&](int ch, int s) {
        const uint32_t sb = smb + s * kStageB;
        const int k0 = ch * kChunk;
        #pragma unroll
        for (int p = 0; p < 4; p++)
            cp16(sb + aoff0 + p * 16, abase + k0 + p * 8);
        #pragma unroll
        for (int p = 0; p < 4; p++)
            cp16(sb + boff0 + p * (16 * kBStrH * 2),
                 bbase + (size_t)(k0 + 16 * p) * kH);
    };
    issue(0, 0); cp_commit();
    issue(1, 1); cp_commit();

    for (int ch = 0; ch < NCH; ch++) {
        cp_wait1();
        __syncthreads();
        if (ch + 2 < NCH) { issue(ch + 2, (ch + 2) % 3); }
        cp_commit();
        const uint32_t sA = smb + (ch % 3) * kStageB;
        const uint32_t sB = sA + kAStageH * 2;
        #pragma unroll
        for (int ks = 0; ks < kChunk; ks += 16) {
            uint32_t a[2][4];
            #pragma unroll
            for (int mt = 0; mt < 2; mt++)
                ldsm4(a[mt], sA + (aF + mt * 16 * kAStrH + ks) * 2);
            #pragma unroll
            for (int blk = 0; blk < 4; blk++) {
                uint32_t b[4];
                ldsm4t(b, sB + (bF + ks * kBStrH + nw + blk * 16) * 2);
                #pragma unroll
                for (int sub = 0; sub < 2; sub++) {
                    int nt = blk * 2 + sub;
                    #pragma unroll
                    for (int mt = 0; mt < 2; mt++)
                        mma16(c[mt][nt], a[mt], b[sub * 2], b[sub * 2 + 1]);
                }
            }
        }
    }

    #pragma unroll
    for (int mt = 0; mt < 2; mt++) {
        #pragma unroll
        for (int pair = 0; pair < 2; pair++) {
            int r = row0 + mb + mt * 16 + qr + pair * 8;
            if (r < cnt) {
                __half* op = g_o + ((size_t)e * kT + r) * kH + col0 + nw;
                #pragma unroll
                for (int nt = 0; nt < 8; nt++) {
                    *(__half2*)&op[nt * 8 + 2 * qc] =
                        __floats2half2_rn(c[mt][nt][pair * 2 + 0],
                                          c[mt][nt][pair * 2 + 1]);
                }
            }
        }
    }
}

// ---------------------------------------------------------------------------
// Combine: out[t] = sum of 4 routed + 2 shared fp16 partial rows (fp32 sum).
__global__ __launch_bounds__(256) void combine_kernel(float* __restrict__ out) {
    const int t = blockIdx.x;
    const int c = threadIdx.x * 4;
    int s[6];
    s[0] = g_tslot[t * kTopK + 0]; s[1] = g_tslot[t * kTopK + 1];
    s[2] = g_tslot[t * kTopK + 2]; s[3] = g_tslot[t * kTopK + 3];
    s[4] = kE * kT + t;            s[5] = (kE + 1) * kT + t;
    float2 acc0 = make_float2(0.f, 0.f), acc1 = make_float2(0.f, 0.f);
    #pragma unroll
    for (int i = 0; i < 6; i++) {
        const __half2* p = (const __half2*)&g_o[(size_t)s[i] * kH + c];
        float2 v0 = __half22float2(p[0]);
        float2 v1 = __half22float2(p[1]);
        acc0.x += v0.x; acc0.y += v0.y;
        acc1.x += v1.x; acc1.y += v1.y;
    }
    float4 r; r.x = acc0.x; r.y = acc0.y; r.z = acc1.x; r.w = acc1.y;
    *(float4*)&out[(size_t)t * kH + c] = r;
}

// ---------------------------------------------------------------------------
extern "C" void kernel_launch(void* const* d_in, const int* in_sizes, int n_in,
                              void* d_out, int out_size) {
    const float* x   = (const float*)d_in[0];
    const float* rw  = (const float*)d_in[1];
    const float* eb  = (const float*)d_in[2];
    const float* wg  = (const float*)d_in[3];
    const float* wu  = (const float*)d_in[4];
    const float* wd  = (const float*)d_in[5];
    const float* swg = (const float*)d_in[6];
    const float* swu = (const float*)d_in[7];
    const float* swd = (const float*)d_in[8];
    float* out = (float*)d_out;

    cudaFuncSetAttribute(gateup_v9, cudaFuncAttributeMaxDynamicSharedMemorySize, kSmem);
    cudaFuncSetAttribute(down_v9,   cudaFuncAttributeMaxDynamicSharedMemorySize, kSmem);

    init_kernel<<<4, 256>>>();
    front_kernel<<<kT + kPreBlocks, 512>>>(x, rw, eb,
                                           (const float4*)wg, (const float4*)wu,
                                           (const float4*)swg, (const float4*)swu);
    gateup_v9<<<dim3(8, 8, kEAll + 2), 256, kSmem>>>((const float4*)wd,
                                                     (const float4*)swd);
    down_v9<<<dim3(8, 8, kEAll), 256, kSmem>>>();
    combine_kernel<<<kT, 256>>>(out);
}